// round 12
// baseline (speedup 1.0000x reference)
#include <cuda_runtime.h>
#include <cuda_fp16.h>
#include <math.h>
#include <stdint.h>

// B=1024, D=512, N=16, H=512, M = N*B = 16384
#define DD   512
#define NN   16
#define HH   512
#define MTOT 16384

// Slotted fp16 fragment files (u32 = packed half2).
// A files: [tile(128)][kc(16)][slot(16)][128]; slot = mf*2+ks.
// B files: [blk][kc(16)][slot(16)][128];     slot = n16*2+ks.
__device__ uint32_t g_A1[128 * 16 * 16 * 128];   // x (gathered), GEMM1 A
__device__ uint32_t g_A2[128 * 16 * 16 * 128];   // lrelu(X@Ws1+bs1), GEMM2 A
__device__ uint32_t g_A3[128 * 16 * 16 * 128];   // shared, GEMM3 A (r-ordered)
__device__ uint32_t g_WB1[4  * 16 * 16 * 128];   // Ws1 slotted
__device__ uint32_t g_WB2[4  * 16 * 16 * 128];   // Ws2 slotted
__device__ uint32_t g_Bh [64 * 16 * 16 * 128];   // Wc1 slotted [n*4+hb]

__device__ __forceinline__ float lrelu(float v) { return v >= 0.f ? v : 0.1f * v; }
__device__ __forceinline__ uint32_t pack_h2(float lo, float hi) {
    __half2 h = __floats2half2_rn(lo, hi);
    return *reinterpret_cast<uint32_t*>(&h);
}
__device__ __forceinline__ uint32_t smem_u32(const void* p) {
    uint32_t a;
    asm("{ .reg .u64 t; cvta.to.shared.u64 t, %1; cvt.u32.u64 %0, t; }" : "=r"(a) : "l"(p));
    return a;
}
__device__ __forceinline__ void cpcg16(uint32_t dst, const void* src) {
    asm volatile("cp.async.cg.shared.global [%0], [%1], 16;" :: "r"(dst), "l"(src));
}
__device__ __forceinline__ void cp_commit() {
    asm volatile("cp.async.commit_group;" ::: "memory");
}
template <int N>
__device__ __forceinline__ void cp_wait() {
    asm volatile("cp.async.wait_group %0;" :: "n"(N) : "memory");
}
__device__ __forceinline__ void mma16h(float* c, const uint32_t* a,
                                       uint32_t b0, uint32_t b1) {
    asm volatile(
        "mma.sync.aligned.m16n8k16.row.col.f32.f16.f16.f32 "
        "{%0,%1,%2,%3}, {%4,%5,%6,%7}, {%8,%9}, {%0,%1,%2,%3};"
        : "+f"(c[0]), "+f"(c[1]), "+f"(c[2]), "+f"(c[3])
        : "r"(a[0]), "r"(a[1]), "r"(a[2]), "r"(a[3]), "r"(b0), "r"(b1));
}

#define SLOTU 128
#define BUFU  2048          // u32 per (kc) buffer: 16 slots * 128
#define G12_SMEM 49152      // gemm12: 3 stages x (A 8KB + B 8KB)

// ===========================================================================
// Prep kernels (R11-verbatim).
// ===========================================================================
__global__ __launch_bounds__(256)
void prep_xA_kernel(const float* __restrict__ x)
{
    int e = blockIdx.x * 256 + threadIdx.x;        // < 4194304
    int i128 = e & 127, s = (e >> 7) & 15, kc = (e >> 11) & 15, tile = e >> 15;
    int mf = s >> 1, ks = s & 1;
    int t = i128 >> 2, j = i128 & 3;
    int r = tile * 128 + mf * 16 + ((j & 1) << 3) + (t >> 2);
    int k = kc * 32 + ks * 16 + (((j >> 1) & 1) << 3) + 2 * (t & 3);
    const float* xb = x + (size_t)(r >> 4) * (DD * NN) + (r & 15);
    g_A1[e] = pack_h2(xb[(size_t)k * NN], xb[(size_t)(k + 1) * NN]);
}

__global__ __launch_bounds__(256)
void prep_wB_kernel(const float* __restrict__ W, uint32_t* __restrict__ dst)
{
    int e = blockIdx.x * 256 + threadIdx.x;        // < 131072
    int i128 = e & 127, s = (e >> 7) & 15, kc = (e >> 11) & 15, hb = e >> 15;
    int n16 = s >> 1, ks = s & 1;
    int t = i128 >> 2, j = i128 & 3;
    int nc = hb * 128 + n16 * 16 + (((j >> 1) & 1) << 3) + (t >> 2);
    int k  = kc * 32 + ks * 16 + ((j & 1) << 3) + 2 * (t & 3);
    dst[e] = pack_h2(W[(size_t)k * DD + nc], W[(size_t)(k + 1) * DD + nc]);
}

__global__ __launch_bounds__(256)
void prep_slotB_kernel(const float* __restrict__ Wc1)
{
    int e = blockIdx.x * 256 + threadIdx.x;        // < 2097152
    int i128 = e & 127, s = (e >> 7) & 15, kc = (e >> 11) & 15;
    int hb = (e >> 15) & 3, n = e >> 17;
    int n16 = s >> 1, ks = s & 1;
    int t = i128 >> 2, j = i128 & 3;
    int nc = hb * 128 + n16 * 16 + (((j >> 1) & 1) << 3) + (t >> 2);
    int k  = kc * 32 + ks * 16 + ((j & 1) << 3) + 2 * (t & 3);
    const float* W = Wc1 + (size_t)n * DD * HH;
    g_Bh[e] = pack_h2(W[(size_t)k * HH + nc], W[(size_t)(k + 1) * HH + nc]);
}

// ===========================================================================
// gemm12 core (R11-verbatim): 3-stage pipeline, 4 warps 64x64, 128 threads.
// ===========================================================================
struct Core {
    const uint32_t* srcA;
    const uint32_t* srcB;
    uint32_t* Ab[3];
    uint32_t* Bb[3];
    int tid, lane, wm, wn;

    __device__ __forceinline__ void stage(int kc) {
        const int buf = kc % 3;
        const uint32_t* sa = srcA + kc * BUFU;
        const uint32_t* sb = srcB + kc * BUFU;
        uint32_t da = smem_u32(Ab[buf]);
        uint32_t db = smem_u32(Bb[buf]);
        #pragma unroll
        for (int i = 0; i < 4; i++) {
            int ch = tid + i * 128;
            cpcg16(da + ch * 16, sa + ch * 4);
            cpcg16(db + ch * 16, sb + ch * 4);
        }
        cp_commit();
    }

    __device__ __forceinline__ void run(float c[4][8][4]) {
        stage(0); stage(1); stage(2);
        for (int kc = 0; kc < 16; kc++) {
            if (kc <= 13)      cp_wait<2>();
            else if (kc == 14) cp_wait<1>();
            else               cp_wait<0>();
            __syncthreads();
            const uint32_t* Asl = Ab[kc % 3];
            const uint32_t* Bsl = Bb[kc % 3];
            #pragma unroll
            for (int ks = 0; ks < 2; ks++) {
                uint4 af[4];
                #pragma unroll
                for (int mfl = 0; mfl < 4; mfl++)
                    af[mfl] = *reinterpret_cast<const uint4*>(
                        &Asl[((wm * 4 + mfl) * 2 + ks) * SLOTU + lane * 4]);
                uint4 bf[4];
                #pragma unroll
                for (int np = 0; np < 4; np++)
                    bf[np] = *reinterpret_cast<const uint4*>(
                        &Bsl[((wn * 4 + np) * 2 + ks) * SLOTU + lane * 4]);
                #pragma unroll
                for (int np = 0; np < 4; np++) {
                    #pragma unroll
                    for (int mfl = 0; mfl < 4; mfl++) {
                        const uint32_t* aa = reinterpret_cast<const uint32_t*>(&af[mfl]);
                        mma16h(c[mfl][2 * np + 0], aa, bf[np].x, bf[np].y);
                        mma16h(c[mfl][2 * np + 1], aa, bf[np].z, bf[np].w);
                    }
                }
            }
            __syncthreads();
            if (kc + 3 < 16) stage(kc + 3);
        }
    }
};

// ===========================================================================
// GEMM1/2 (R11-verbatim): chained slotted-A output.
// ===========================================================================
template <int MODE>
__global__ __launch_bounds__(128)
void gemm12_f16(const float* __restrict__ bias)
{
    extern __shared__ uint32_t sm[];
    const int tid  = threadIdx.x;
    const int lane = tid & 31;
    const int wid  = tid >> 5;
    const int tig  = lane & 3;
    const int wm   = wid >> 1;
    const int wn   = wid & 1;
    const int tile = blockIdx.x;
    const int col0 = blockIdx.y * 128;

    const uint32_t* srcA = (MODE == 0 ? g_A1 : g_A2) + (size_t)tile * 16 * BUFU;
    const uint32_t* srcB = (MODE == 0 ? g_WB1 : g_WB2) + (size_t)blockIdx.y * 16 * BUFU;
    uint32_t* dstA = (MODE == 0 ? g_A2 : g_A3) + (size_t)tile * 16 * BUFU;

    float c[4][8][4];
    #pragma unroll
    for (int i = 0; i < 4; i++)
        #pragma unroll
        for (int j = 0; j < 8; j++)
            #pragma unroll
            for (int q = 0; q < 4; q++) c[i][j][q] = 0.f;

    Core core{srcA, srcB, {sm, sm + BUFU, sm + 2 * BUFU},
              {sm + 3 * BUFU, sm + 4 * BUFU, sm + 5 * BUFU}, tid, lane, wm, wn};
    core.run(c);

    #pragma unroll
    for (int mf = 0; mf < 4; mf++) {
        #pragma unroll
        for (int q = 0; q < 4; q++) {
            const int nf0 = 2 * q, nf1 = 2 * q + 1;
            const int K = col0 + wn * 64 + q * 16 + 2 * tig;
            const float b0 = bias[K],     b1 = bias[K + 1];
            const float b8 = bias[K + 8], b9 = bias[K + 9];
            const int kc_o = (col0 >> 5) + wn * 2 + (q >> 1);
            const int slot = (wm * 4 + mf) * 2 + (q & 1);
            uint4 v;
            v.x = pack_h2(lrelu(c[mf][nf0][0] + b0), lrelu(c[mf][nf0][1] + b1));
            v.y = pack_h2(lrelu(c[mf][nf0][2] + b0), lrelu(c[mf][nf0][3] + b1));
            v.z = pack_h2(lrelu(c[mf][nf1][0] + b8), lrelu(c[mf][nf1][1] + b9));
            v.w = pack_h2(lrelu(c[mf][nf1][2] + b8), lrelu(c[mf][nf1][3] + b9));
            *reinterpret_cast<uint4*>(
                &dstA[(size_t)(kc_o * 16 + slot) * SLOTU + lane * 4]) = v;
        }
    }
}

// ===========================================================================
// GEMM3 v2: CTA = (tile, n), 256 threads / 8 warps (2x4 grid, 64x64 tiles).
// Two iterations of 256 h-columns each. A (128KB) staged during it=0, kept
// SMEM-resident and reused in it=1. Full h-sum in-CTA: no atomics/zero;
// bc2 + sigmoid-diagonal fused.
// smem: A 16kc x 8KB = 128KB, B 3 stages x 16KB = 48KB -> 176KB.
// ===========================================================================
#define G3A_U   (16 * BUFU)          // 32768 u32 resident A
#define G3B_U   (3 * 2 * BUFU)       // 12288 u32 B stages (2 blocks per stage)
#define G3_SMEM ((G3A_U + G3B_U) * 4)   // 180224 B

__global__ __launch_bounds__(256, 1)
void gemm_head_tc(const float* __restrict__ bc1,
                  const float* __restrict__ Wc2,
                  const float* __restrict__ bc2,
                  float* __restrict__ out)
{
    extern __shared__ uint32_t sm[];
    uint32_t* Asm = sm;                    // resident A
    uint32_t* Bsm = sm + G3A_U;            // B ring: stage s at Bsm + (s%3)*4096

    const int tid  = threadIdx.x;          // 256 threads
    const int lane = tid & 31;
    const int wid  = tid >> 5;
    const int g    = lane >> 2;
    const int tig  = lane & 3;
    const int wm   = wid >> 2;             // 0..1 (64 rows)
    const int wn   = wid & 3;              // 0..3 (64 of 256 cols)
    const int tile = blockIdx.x;
    const int n    = blockIdx.y;
    const int row0 = tile * 128;

    const uint32_t* __restrict__ srcA = g_A3 + (size_t)tile * 16 * BUFU;

    auto stage = [&](int si) {             // si = it*16 + kc, 0..31
        const int kc = si & 15, it = si >> 4;
        if (si < 16) {                     // stage A[kc] (resident)
            const uint32_t* sa = srcA + kc * BUFU;
            uint32_t da = smem_u32(Asm + kc * BUFU);
            #pragma unroll
            for (int i = 0; i < 2; i++) {
                int ch = tid + i * 256;    // 0..511 16B-chunks
                cpcg16(da + ch * 16, sa + ch * 4);
            }
        }
        const uint32_t* sb0 = g_Bh + ((size_t)(n * 4 + it * 2 + 0) * 16 + kc) * BUFU;
        const uint32_t* sb1 = g_Bh + ((size_t)(n * 4 + it * 2 + 1) * 16 + kc) * BUFU;
        uint32_t db = smem_u32(Bsm + (si % 3) * (2 * BUFU));
        #pragma unroll
        for (int i = 0; i < 2; i++) {
            int ch = tid + i * 256;
            cpcg16(db + ch * 16, sb0 + ch * 4);
            cpcg16(db + (512 + ch) * 16, sb1 + ch * 4);
        }
        cp_commit();
    };

    float p[8];
    #pragma unroll
    for (int i = 0; i < 8; i++) p[i] = 0.f;

    float c[4][8][4];
    #pragma unroll
    for (int i = 0; i < 4; i++)
        #pragma unroll
        for (int j = 0; j < 8; j++)
            #pragma unroll
            for (int q = 0; q < 4; q++) c[i][j][q] = 0.f;

    stage(0); stage(1); stage(2);
    for (int si = 0; si < 32; si++) {
        if (si <= 29)      cp_wait<2>();
        else if (si == 30) cp_wait<1>();
        else               cp_wait<0>();
        __syncthreads();
        const int kc = si & 15, it = si >> 4;
        const uint32_t* Asl = Asm + kc * BUFU;
        const uint32_t* Bsl = Bsm + (si % 3) * (2 * BUFU) + (wn >> 1) * BUFU;
        #pragma unroll
        for (int ks = 0; ks < 2; ks++) {
            uint4 af[4];
            #pragma unroll
            for (int mfl = 0; mfl < 4; mfl++)
                af[mfl] = *reinterpret_cast<const uint4*>(
                    &Asl[((wm * 4 + mfl) * 2 + ks) * SLOTU + lane * 4]);
            uint4 bf[4];
            #pragma unroll
            for (int np = 0; np < 4; np++)
                bf[np] = *reinterpret_cast<const uint4*>(
                    &Bsl[(((wn & 1) * 4 + np) * 2 + ks) * SLOTU + lane * 4]);
            #pragma unroll
            for (int np = 0; np < 4; np++) {
                #pragma unroll
                for (int mfl = 0; mfl < 4; mfl++) {
                    const uint32_t* aa = reinterpret_cast<const uint32_t*>(&af[mfl]);
                    mma16h(c[mfl][2 * np + 0], aa, bf[np].x, bf[np].y);
                    mma16h(c[mfl][2 * np + 1], aa, bf[np].z, bf[np].w);
                }
            }
        }
        __syncthreads();
        if (si + 3 < 32) stage(si + 3);

        if (kc == 15) {
            // partial epilogue for this 256-col iteration; reset accumulators
            #pragma unroll
            for (int nf = 0; nf < 8; nf++) {
                int h = it * 256 + (wn >> 1) * 128 + (wn & 1) * 64 + nf * 8 + 2 * tig;
                float b1a = bc1[n * HH + h],     b1b = bc1[n * HH + h + 1];
                float w2a = Wc2[n * HH + h],     w2b = Wc2[n * HH + h + 1];
                #pragma unroll
                for (int mf = 0; mf < 4; mf++) {
                    p[2 * mf + 0] += lrelu(c[mf][nf][0] + b1a) * w2a
                                   + lrelu(c[mf][nf][1] + b1b) * w2b;
                    p[2 * mf + 1] += lrelu(c[mf][nf][2] + b1a) * w2a
                                   + lrelu(c[mf][nf][3] + b1b) * w2b;
                    c[mf][nf][0] = 0.f; c[mf][nf][1] = 0.f;
                    c[mf][nf][2] = 0.f; c[mf][nf][3] = 0.f;
                }
            }
        }
    }

    // cross-warp (wn) combine via smem, then direct store with bc2 + sigmoid
    float* red = reinterpret_cast<float*>(Bsm);      // 4 x 128 floats
    #pragma unroll
    for (int i = 0; i < 8; i++) {
        float v = p[i];
        v += __shfl_xor_sync(0xffffffffu, v, 1);
        v += __shfl_xor_sync(0xffffffffu, v, 2);
        p[i] = v;
    }
    __syncthreads();
    if (tig == 0) {
        #pragma unroll
        for (int i = 0; i < 8; i++) {
            int mf = i >> 1, half = i & 1;
            int row = wm * 64 + mf * 16 + g + half * 8;
            red[wn * 128 + row] = p[i];
        }
    }
    __syncthreads();
    if (tid < 128) {
        int r = row0 + tid;
        float L = red[tid] + red[128 + tid] + red[256 + tid] + red[384 + tid]
                + bc2[n];
        int M = (r & 15) * 1024 + (r >> 4);
        float* full = out + MTOT;
        full[M * NN + n] = L;
        if ((r & 15) == n)                        // diagonal: b = r>>4
            out[(r >> 4) * NN + n] = 1.f / (1.f + expf(-L));
    }
}

extern "C" void kernel_launch(void* const* d_in, const int* in_sizes, int n_in,
                              void* d_out, int out_size)
{
    const float* x   = (const float*)d_in[0];
    const float* Ws1 = (const float*)d_in[1];
    const float* bs1 = (const float*)d_in[2];
    const float* Ws2 = (const float*)d_in[3];
    const float* bs2 = (const float*)d_in[4];
    const float* Wc1 = (const float*)d_in[5];
    const float* bc1 = (const float*)d_in[6];
    const float* Wc2 = (const float*)d_in[7];
    const float* bc2 = (const float*)d_in[8];
    float* out = (float*)d_out;

    uint32_t *wb1, *wb2;
    cudaGetSymbolAddress((void**)&wb1, g_WB1);
    cudaGetSymbolAddress((void**)&wb2, g_WB2);

    cudaFuncSetAttribute(gemm12_f16<0>, cudaFuncAttributeMaxDynamicSharedMemorySize, G12_SMEM);
    cudaFuncSetAttribute(gemm12_f16<1>, cudaFuncAttributeMaxDynamicSharedMemorySize, G12_SMEM);
    cudaFuncSetAttribute(gemm_head_tc,  cudaFuncAttributeMaxDynamicSharedMemorySize, G3_SMEM);

    dim3 blk(256);
    prep_xA_kernel<<<4194304 / 256, blk>>>(x);
    prep_wB_kernel<<<131072 / 256, blk>>>(Ws1, wb1);
    prep_wB_kernel<<<131072 / 256, blk>>>(Ws2, wb2);
    prep_slotB_kernel<<<2097152 / 256, blk>>>(Wc1);
    gemm12_f16<0><<<dim3(128, 4), dim3(128), G12_SMEM>>>(bs1);
    gemm12_f16<1><<<dim3(128, 4), dim3(128), G12_SMEM>>>(bs2);
    gemm_head_tc<<<dim3(128, NN), dim3(256), G3_SMEM>>>(bc1, Wc2, bc2, out);
}

// round 13
// speedup vs baseline: 1.6919x; 1.6919x over previous
#include <cuda_runtime.h>
#include <cuda_fp16.h>
#include <math.h>
#include <stdint.h>

// B=1024, D=512, N=16, H=512, M = N*B = 16384
#define DD   512
#define NN   16
#define HH   512
#define MTOT 16384

// Slotted fp16 fragment files (u32 = packed half2).
// A files: [tile(128)][kc(16)][slot(16)][128]; slot = mf*2+ks.
// B files: [blk][kc(16)][slot(16)][128];     slot = n16*2+ks.
__device__ uint32_t g_A1[128 * 16 * 16 * 128];   // x (gathered), GEMM1 A
__device__ uint32_t g_A2[128 * 16 * 16 * 128];   // lrelu(X@Ws1+bs1), GEMM2 A
__device__ uint32_t g_A3[128 * 16 * 16 * 128];   // shared, GEMM3 A (r-ordered)
__device__ uint32_t g_WB1[4  * 16 * 16 * 128];   // Ws1 slotted
__device__ uint32_t g_WB2[4  * 16 * 16 * 128];   // Ws2 slotted
__device__ uint32_t g_Bh [64 * 16 * 16 * 128];   // Wc1 slotted [n*4+hb]

__device__ __forceinline__ float lrelu(float v) { return v >= 0.f ? v : 0.1f * v; }
__device__ __forceinline__ uint32_t pack_h2(float lo, float hi) {
    __half2 h = __floats2half2_rn(lo, hi);
    return *reinterpret_cast<uint32_t*>(&h);
}
__device__ __forceinline__ uint32_t smem_u32(const void* p) {
    uint32_t a;
    asm("{ .reg .u64 t; cvta.to.shared.u64 t, %1; cvt.u32.u64 %0, t; }" : "=r"(a) : "l"(p));
    return a;
}
__device__ __forceinline__ void cpcg16(uint32_t dst, const void* src) {
    asm volatile("cp.async.cg.shared.global [%0], [%1], 16;" :: "r"(dst), "l"(src));
}
__device__ __forceinline__ void cp_commit() {
    asm volatile("cp.async.commit_group;" ::: "memory");
}
template <int N>
__device__ __forceinline__ void cp_wait() {
    asm volatile("cp.async.wait_group %0;" :: "n"(N) : "memory");
}
__device__ __forceinline__ void mma16h(float* c, const uint32_t* a,
                                       uint32_t b0, uint32_t b1) {
    asm volatile(
        "mma.sync.aligned.m16n8k16.row.col.f32.f16.f16.f32 "
        "{%0,%1,%2,%3}, {%4,%5,%6,%7}, {%8,%9}, {%0,%1,%2,%3};"
        : "+f"(c[0]), "+f"(c[1]), "+f"(c[2]), "+f"(c[3])
        : "r"(a[0]), "r"(a[1]), "r"(a[2]), "r"(a[3]), "r"(b0), "r"(b1));
}

#define SLOTU 128
#define BUFU  2048          // u32 per (kc) buffer: 16 slots * 128
#define RING_SMEM 65536     // 4-ring x (A 8KB + B 8KB)

// ===========================================================================
// Fused prep + zero kernel (all regions independent).
// Slot maps are R11-verbatim.
// ===========================================================================
__global__ __launch_bounds__(256)
void prep_all_kernel(const float* __restrict__ x,
                     const float* __restrict__ Ws1,
                     const float* __restrict__ Ws2,
                     const float* __restrict__ Wc1,
                     float* __restrict__ out)
{
    const int blk = blockIdx.x;
    const int tid = threadIdx.x;

    if (blk < 16384) {
        // --- prep_xA: x (B,D,N) -> g_A1 (rows r = b*16+n) ---
        int e = blk * 256 + tid;                   // < 4194304
        int i128 = e & 127, s = (e >> 7) & 15, kc = (e >> 11) & 15, tile = e >> 15;
        int mf = s >> 1, ks = s & 1;
        int t = i128 >> 2, j = i128 & 3;
        int r = tile * 128 + mf * 16 + ((j & 1) << 3) + (t >> 2);
        int k = kc * 32 + ks * 16 + (((j >> 1) & 1) << 3) + 2 * (t & 3);
        const float* xb = x + (size_t)(r >> 4) * (DD * NN) + (r & 15);
        g_A1[e] = pack_h2(xb[(size_t)k * NN], xb[(size_t)(k + 1) * NN]);
    } else if (blk < 17408) {
        // --- prep_wB for Ws1 / Ws2 ---
        int region = blk - 16384;                  // 0..1023
        const float* W = (region < 512) ? Ws1 : Ws2;
        uint32_t* dst  = (region < 512) ? g_WB1 : g_WB2;
        int e = (region & 511) * 256 + tid;        // < 131072
        int i128 = e & 127, s = (e >> 7) & 15, kc = (e >> 11) & 15, hb = e >> 15;
        int n16 = s >> 1, ks = s & 1;
        int t = i128 >> 2, j = i128 & 3;
        int nc = hb * 128 + n16 * 16 + (((j >> 1) & 1) << 3) + (t >> 2);
        int k  = kc * 32 + ks * 16 + ((j & 1) << 3) + 2 * (t & 3);
        dst[e] = pack_h2(W[(size_t)k * DD + nc], W[(size_t)(k + 1) * DD + nc]);
    } else if (blk < 25600) {
        // --- prep_slotB: Wc1 [n][K][H] -> g_Bh ---
        int e = (blk - 17408) * 256 + tid;         // < 2097152
        int i128 = e & 127, s = (e >> 7) & 15, kc = (e >> 11) & 15;
        int hb = (e >> 15) & 3, n = e >> 17;
        int n16 = s >> 1, ks = s & 1;
        int t = i128 >> 2, j = i128 & 3;
        int nc = hb * 128 + n16 * 16 + (((j >> 1) & 1) << 3) + (t >> 2);
        int k  = kc * 32 + ks * 16 + ((j & 1) << 3) + 2 * (t & 3);
        const float* W = Wc1 + (size_t)n * DD * HH;
        g_Bh[e] = pack_h2(W[(size_t)k * HH + nc], W[(size_t)(k + 1) * HH + nc]);
    } else {
        // --- zero full_out accumulation region ---
        int i = (blk - 25600) * 256 + tid;         // < 262144
        if (i < MTOT * NN) (out + MTOT)[i] = 0.f;
    }
}

// ===========================================================================
// Shared mainloop: 4-deep ring, ONE sync per kc, fp16 m16n8k16,
// 4 warps 64x64, 128 threads.
// Hazard proof: wait<2> with commits g0..g(kc+2) => group kc complete.
// stage(kc+3) writes buf (kc+3)&3 == (kc-1)&3, whose consumption (iter kc-1)
// finished before this iteration's top sync.
// ===========================================================================
struct Core {
    const uint32_t* srcA;
    const uint32_t* srcB;
    uint32_t* Ab[4];
    uint32_t* Bb[4];
    int tid, lane, wm, wn;

    __device__ __forceinline__ void stage(int kc) {
        const int buf = kc & 3;
        const uint32_t* sa = srcA + kc * BUFU;
        const uint32_t* sb = srcB + kc * BUFU;
        uint32_t da = smem_u32(Ab[buf]);
        uint32_t db = smem_u32(Bb[buf]);
        #pragma unroll
        for (int i = 0; i < 4; i++) {
            int ch = tid + i * 128;
            cpcg16(da + ch * 16, sa + ch * 4);
            cpcg16(db + ch * 16, sb + ch * 4);
        }
        cp_commit();
    }

    __device__ __forceinline__ void run(float c[4][8][4]) {
        stage(0); stage(1); stage(2);
        for (int kc = 0; kc < 16; kc++) {
            if (kc <= 13)      cp_wait<2>();
            else if (kc == 14) cp_wait<1>();
            else               cp_wait<0>();
            __syncthreads();
            const uint32_t* Asl = Ab[kc & 3];
            const uint32_t* Bsl = Bb[kc & 3];
            #pragma unroll
            for (int ks = 0; ks < 2; ks++) {
                uint4 af[4];
                #pragma unroll
                for (int mfl = 0; mfl < 4; mfl++)
                    af[mfl] = *reinterpret_cast<const uint4*>(
                        &Asl[((wm * 4 + mfl) * 2 + ks) * SLOTU + lane * 4]);
                uint4 bf[4];
                #pragma unroll
                for (int np = 0; np < 4; np++)
                    bf[np] = *reinterpret_cast<const uint4*>(
                        &Bsl[((wn * 4 + np) * 2 + ks) * SLOTU + lane * 4]);
                #pragma unroll
                for (int np = 0; np < 4; np++) {
                    #pragma unroll
                    for (int mfl = 0; mfl < 4; mfl++) {
                        const uint32_t* aa = reinterpret_cast<const uint32_t*>(&af[mfl]);
                        mma16h(c[mfl][2 * np + 0], aa, bf[np].x, bf[np].y);
                        mma16h(c[mfl][2 * np + 1], aa, bf[np].z, bf[np].w);
                    }
                }
            }
            if (kc + 3 < 16) stage(kc + 3);
        }
    }
};

// ===========================================================================
// GEMM1/2 (R11 structure + 4-ring core): chained slotted-A output.
// ===========================================================================
template <int MODE>
__global__ __launch_bounds__(128)
void gemm12_f16(const float* __restrict__ bias)
{
    extern __shared__ uint32_t sm[];
    const int tid  = threadIdx.x;
    const int lane = tid & 31;
    const int wid  = tid >> 5;
    const int tig  = lane & 3;
    const int wm   = wid >> 1;
    const int wn   = wid & 1;
    const int tile = blockIdx.x;
    const int col0 = blockIdx.y * 128;

    const uint32_t* srcA = (MODE == 0 ? g_A1 : g_A2) + (size_t)tile * 16 * BUFU;
    const uint32_t* srcB = (MODE == 0 ? g_WB1 : g_WB2) + (size_t)blockIdx.y * 16 * BUFU;
    uint32_t* dstA = (MODE == 0 ? g_A2 : g_A3) + (size_t)tile * 16 * BUFU;

    float c[4][8][4];
    #pragma unroll
    for (int i = 0; i < 4; i++)
        #pragma unroll
        for (int j = 0; j < 8; j++)
            #pragma unroll
            for (int q = 0; q < 4; q++) c[i][j][q] = 0.f;

    Core core{srcA, srcB,
              {sm, sm + BUFU, sm + 2 * BUFU, sm + 3 * BUFU},
              {sm + 4 * BUFU, sm + 5 * BUFU, sm + 6 * BUFU, sm + 7 * BUFU},
              tid, lane, wm, wn};
    core.run(c);

    #pragma unroll
    for (int mf = 0; mf < 4; mf++) {
        #pragma unroll
        for (int q = 0; q < 4; q++) {
            const int nf0 = 2 * q, nf1 = 2 * q + 1;
            const int K = col0 + wn * 64 + q * 16 + 2 * tig;
            const float b0 = bias[K],     b1 = bias[K + 1];
            const float b8 = bias[K + 8], b9 = bias[K + 9];
            const int kc_o = (col0 >> 5) + wn * 2 + (q >> 1);
            const int slot = (wm * 4 + mf) * 2 + (q & 1);
            uint4 v;
            v.x = pack_h2(lrelu(c[mf][nf0][0] + b0), lrelu(c[mf][nf0][1] + b1));
            v.y = pack_h2(lrelu(c[mf][nf0][2] + b0), lrelu(c[mf][nf0][3] + b1));
            v.z = pack_h2(lrelu(c[mf][nf1][0] + b8), lrelu(c[mf][nf1][1] + b9));
            v.w = pack_h2(lrelu(c[mf][nf1][2] + b8), lrelu(c[mf][nf1][3] + b9));
            *reinterpret_cast<uint4*>(
                &dstA[(size_t)(kc_o * 16 + slot) * SLOTU + lane * 4]) = v;
        }
    }
}

// ===========================================================================
// GEMM3 (R11 structure + 4-ring core): grid (128 tiles, 4 hb, 16 n),
// 128 threads, fused lrelu(+bc1)*Wc2 epilogue, shfl reduce, atomicAdd
// with M = (r&15)*1024 + (r>>4).
// ===========================================================================
__global__ __launch_bounds__(128)
void gemm_head_tc(const float* __restrict__ bc1,
                  const float* __restrict__ Wc2,
                  float* __restrict__ logits)
{
    extern __shared__ uint32_t sm[];
    const int tid  = threadIdx.x;
    const int lane = tid & 31;
    const int wid  = tid >> 5;
    const int g    = lane >> 2;
    const int tig  = lane & 3;
    const int wm   = wid >> 1;
    const int wn   = wid & 1;
    const int tile = blockIdx.x;
    const int hb   = blockIdx.y;
    const int n    = blockIdx.z;
    const int row0 = tile * 128;
    const int h0   = hb * 128;

    const uint32_t* srcA = g_A3 + (size_t)tile * 16 * BUFU;
    const uint32_t* srcB = g_Bh + (size_t)(n * 4 + hb) * 16 * BUFU;

    float c[4][8][4];
    #pragma unroll
    for (int i = 0; i < 4; i++)
        #pragma unroll
        for (int j = 0; j < 8; j++)
            #pragma unroll
            for (int q = 0; q < 4; q++) c[i][j][q] = 0.f;

    Core core{srcA, srcB,
              {sm, sm + BUFU, sm + 2 * BUFU, sm + 3 * BUFU},
              {sm + 4 * BUFU, sm + 5 * BUFU, sm + 6 * BUFU, sm + 7 * BUFU},
              tid, lane, wm, wn};
    core.run(c);

    float p[8];
    #pragma unroll
    for (int i = 0; i < 8; i++) p[i] = 0.f;
    #pragma unroll
    for (int nf = 0; nf < 8; nf++) {
        int h = h0 + wn * 64 + nf * 8 + 2 * tig;
        float b1a = bc1[n * HH + h],     b1b = bc1[n * HH + h + 1];
        float w2a = Wc2[n * HH + h],     w2b = Wc2[n * HH + h + 1];
        #pragma unroll
        for (int mf = 0; mf < 4; mf++) {
            p[2 * mf + 0] += lrelu(c[mf][nf][0] + b1a) * w2a
                           + lrelu(c[mf][nf][1] + b1b) * w2b;
            p[2 * mf + 1] += lrelu(c[mf][nf][2] + b1a) * w2a
                           + lrelu(c[mf][nf][3] + b1b) * w2b;
        }
    }
    #pragma unroll
    for (int i = 0; i < 8; i++) {
        float v = p[i];
        v += __shfl_xor_sync(0xffffffffu, v, 1);
        v += __shfl_xor_sync(0xffffffffu, v, 2);
        if (tig == 0) {
            int mf = i >> 1, half = i & 1;
            int r = row0 + wm * 64 + mf * 16 + g + half * 8;
            int M = (r & 15) * 1024 + (r >> 4);
            atomicAdd(&logits[M * NN + n], v);
        }
    }
}

// full_out += bc2; out[b,n] = sigmoid(diagonal of full_out)
__global__ void finalize_kernel(float* __restrict__ out,
                                const float* __restrict__ bc2)
{
    int idx = blockIdx.x * 256 + threadIdx.x;      // < 262144
    int m = idx >> 4, n = idx & 15;
    float* full = out + MTOT;
    float v = full[idx] + bc2[n];
    full[idx] = v;
    if ((m >> 10) == n) {                           // m = n*1024 + b
        int b = m & 1023;
        out[b * NN + n] = 1.f / (1.f + expf(-v));
    }
}

extern "C" void kernel_launch(void* const* d_in, const int* in_sizes, int n_in,
                              void* d_out, int out_size)
{
    const float* x   = (const float*)d_in[0];
    const float* Ws1 = (const float*)d_in[1];
    const float* bs1 = (const float*)d_in[2];
    const float* Ws2 = (const float*)d_in[3];
    const float* bs2 = (const float*)d_in[4];
    const float* Wc1 = (const float*)d_in[5];
    const float* bc1 = (const float*)d_in[6];
    const float* Wc2 = (const float*)d_in[7];
    const float* bc2 = (const float*)d_in[8];
    float* out = (float*)d_out;

    cudaFuncSetAttribute(gemm12_f16<0>, cudaFuncAttributeMaxDynamicSharedMemorySize, RING_SMEM);
    cudaFuncSetAttribute(gemm12_f16<1>, cudaFuncAttributeMaxDynamicSharedMemorySize, RING_SMEM);
    cudaFuncSetAttribute(gemm_head_tc,  cudaFuncAttributeMaxDynamicSharedMemorySize, RING_SMEM);

    dim3 blk(256);
    // fused prep (xA + Ws1 + Ws2 + Wc1 slotting) + zero, one launch
    prep_all_kernel<<<26624, blk>>>(x, Ws1, Ws2, Wc1, out);
    // chained GEMMs
    gemm12_f16<0><<<dim3(128, 4), dim3(128), RING_SMEM>>>(bs1);
    gemm12_f16<1><<<dim3(128, 4), dim3(128), RING_SMEM>>>(bs2);
    gemm_head_tc<<<dim3(128, 4, NN), dim3(128), RING_SMEM>>>(bc1, Wc2, out + MTOT);
    finalize_kernel<<<(MTOT * NN + 255) / 256, blk>>>(out, bc2);
}

// round 14
// speedup vs baseline: 1.7609x; 1.0408x over previous
#include <cuda_runtime.h>
#include <cuda_fp16.h>
#include <math.h>
#include <stdint.h>

// B=1024, D=512, N=16, H=512, M = N*B = 16384
#define DD   512
#define NN   16
#define HH   512
#define MTOT 16384

// Slotted fp16 fragment files (u32 = packed half2).
// A files: [tile(128)][kc(16)][slot(16)][128]; slot = mf*2+ks.
// B files: [blk][kc(16)][slot(16)][128];     slot = n16*2+ks.
__device__ uint32_t g_A1[128 * 16 * 16 * 128];   // x (gathered), GEMM1 A
__device__ uint32_t g_A2[128 * 16 * 16 * 128];   // lrelu(X@Ws1+bs1), GEMM2 A
__device__ uint32_t g_A3[128 * 16 * 16 * 128];   // shared, GEMM3 A (r-ordered)
__device__ uint32_t g_WB1[4  * 16 * 16 * 128];   // Ws1 slotted
__device__ uint32_t g_WB2[4  * 16 * 16 * 128];   // Ws2 slotted
__device__ uint32_t g_Bh [64 * 16 * 16 * 128];   // Wc1 slotted [n*4+hb]

__device__ __forceinline__ float lrelu(float v) { return v >= 0.f ? v : 0.1f * v; }
__device__ __forceinline__ uint32_t pack_h2(float lo, float hi) {
    __half2 h = __floats2half2_rn(lo, hi);
    return *reinterpret_cast<uint32_t*>(&h);
}
__device__ __forceinline__ uint32_t smem_u32(const void* p) {
    uint32_t a;
    asm("{ .reg .u64 t; cvta.to.shared.u64 t, %1; cvt.u32.u64 %0, t; }" : "=r"(a) : "l"(p));
    return a;
}
__device__ __forceinline__ void cpcg16(uint32_t dst, const void* src) {
    asm volatile("cp.async.cg.shared.global [%0], [%1], 16;" :: "r"(dst), "l"(src));
}
__device__ __forceinline__ void cp_commit() {
    asm volatile("cp.async.commit_group;" ::: "memory");
}
template <int N>
__device__ __forceinline__ void cp_wait() {
    asm volatile("cp.async.wait_group %0;" :: "n"(N) : "memory");
}
__device__ __forceinline__ void mma16h(float* c, const uint32_t* a,
                                       uint32_t b0, uint32_t b1) {
    asm volatile(
        "mma.sync.aligned.m16n8k16.row.col.f32.f16.f16.f32 "
        "{%0,%1,%2,%3}, {%4,%5,%6,%7}, {%8,%9}, {%0,%1,%2,%3};"
        : "+f"(c[0]), "+f"(c[1]), "+f"(c[2]), "+f"(c[3])
        : "r"(a[0]), "r"(a[1]), "r"(a[2]), "r"(a[3]), "r"(b0), "r"(b1));
}

#define SLOTU 128
#define BUFU  2048          // u32 per (kc) buffer: 16 slots * 128
#define RING_SMEM 65536     // 4-ring x (A 8KB + B 8KB)

// ===========================================================================
// Fused prep + zero kernel (R13-verbatim).
// ===========================================================================
__global__ __launch_bounds__(256)
void prep_all_kernel(const float* __restrict__ x,
                     const float* __restrict__ Ws1,
                     const float* __restrict__ Ws2,
                     const float* __restrict__ Wc1,
                     float* __restrict__ out)
{
    const int blk = blockIdx.x;
    const int tid = threadIdx.x;

    if (blk < 16384) {
        int e = blk * 256 + tid;                   // < 4194304
        int i128 = e & 127, s = (e >> 7) & 15, kc = (e >> 11) & 15, tile = e >> 15;
        int mf = s >> 1, ks = s & 1;
        int t = i128 >> 2, j = i128 & 3;
        int r = tile * 128 + mf * 16 + ((j & 1) << 3) + (t >> 2);
        int k = kc * 32 + ks * 16 + (((j >> 1) & 1) << 3) + 2 * (t & 3);
        const float* xb = x + (size_t)(r >> 4) * (DD * NN) + (r & 15);
        g_A1[e] = pack_h2(xb[(size_t)k * NN], xb[(size_t)(k + 1) * NN]);
    } else if (blk < 17408) {
        int region = blk - 16384;                  // 0..1023
        const float* W = (region < 512) ? Ws1 : Ws2;
        uint32_t* dst  = (region < 512) ? g_WB1 : g_WB2;
        int e = (region & 511) * 256 + tid;        // < 131072
        int i128 = e & 127, s = (e >> 7) & 15, kc = (e >> 11) & 15, hb = e >> 15;
        int n16 = s >> 1, ks = s & 1;
        int t = i128 >> 2, j = i128 & 3;
        int nc = hb * 128 + n16 * 16 + (((j >> 1) & 1) << 3) + (t >> 2);
        int k  = kc * 32 + ks * 16 + ((j & 1) << 3) + 2 * (t & 3);
        dst[e] = pack_h2(W[(size_t)k * DD + nc], W[(size_t)(k + 1) * DD + nc]);
    } else if (blk < 25600) {
        int e = (blk - 17408) * 256 + tid;         // < 2097152
        int i128 = e & 127, s = (e >> 7) & 15, kc = (e >> 11) & 15;
        int hb = (e >> 15) & 3, n = e >> 17;
        int n16 = s >> 1, ks = s & 1;
        int t = i128 >> 2, j = i128 & 3;
        int nc = hb * 128 + n16 * 16 + (((j >> 1) & 1) << 3) + (t >> 2);
        int k  = kc * 32 + ks * 16 + ((j & 1) << 3) + 2 * (t & 3);
        const float* W = Wc1 + (size_t)n * DD * HH;
        g_Bh[e] = pack_h2(W[(size_t)k * HH + nc], W[(size_t)(k + 1) * HH + nc]);
    } else {
        int i = (blk - 25600) * 256 + tid;         // < 262144
        if (i < MTOT * NN) (out + MTOT)[i] = 0.f;
    }
}

// ===========================================================================
// Shared mainloop: 4-deep ring, one sync per kc, fragment prefetch across ks
// and early stage() issue so LSU overlaps the tensor pipe.
// ===========================================================================
struct Core {
    const uint32_t* srcA;
    const uint32_t* srcB;
    uint32_t* Ab[4];
    uint32_t* Bb[4];
    int tid, lane, wm, wn;

    __device__ __forceinline__ void stage(int kc) {
        const int buf = kc & 3;
        const uint32_t* sa = srcA + kc * BUFU;
        const uint32_t* sb = srcB + kc * BUFU;
        uint32_t da = smem_u32(Ab[buf]);
        uint32_t db = smem_u32(Bb[buf]);
        #pragma unroll
        for (int i = 0; i < 4; i++) {
            int ch = tid + i * 128;
            cpcg16(da + ch * 16, sa + ch * 4);
            cpcg16(db + ch * 16, sb + ch * 4);
        }
        cp_commit();
    }

    __device__ __forceinline__ void ldfrag(const uint32_t* Asl, const uint32_t* Bsl,
                                           int ks, uint4* af, uint4* bf) {
        #pragma unroll
        for (int mfl = 0; mfl < 4; mfl++)
            af[mfl] = *reinterpret_cast<const uint4*>(
                &Asl[((wm * 4 + mfl) * 2 + ks) * SLOTU + lane * 4]);
        #pragma unroll
        for (int np = 0; np < 4; np++)
            bf[np] = *reinterpret_cast<const uint4*>(
                &Bsl[((wn * 4 + np) * 2 + ks) * SLOTU + lane * 4]);
    }

    __device__ __forceinline__ void domma(const uint4* af, const uint4* bf,
                                          float c[4][8][4]) {
        #pragma unroll
        for (int np = 0; np < 4; np++) {
            #pragma unroll
            for (int mfl = 0; mfl < 4; mfl++) {
                const uint32_t* aa = reinterpret_cast<const uint32_t*>(&af[mfl]);
                mma16h(c[mfl][2 * np + 0], aa, bf[np].x, bf[np].y);
                mma16h(c[mfl][2 * np + 1], aa, bf[np].z, bf[np].w);
            }
        }
    }

    __device__ __forceinline__ void run(float c[4][8][4]) {
        stage(0); stage(1); stage(2);
        for (int kc = 0; kc < 16; kc++) {
            if (kc <= 13)      cp_wait<2>();
            else if (kc == 14) cp_wait<1>();
            else               cp_wait<0>();
            __syncthreads();
            const uint32_t* Asl = Ab[kc & 3];
            const uint32_t* Bsl = Bb[kc & 3];
            uint4 af0[4], bf0[4], af1[4], bf1[4];
            ldfrag(Asl, Bsl, 0, af0, bf0);
            if (kc + 3 < 16) stage(kc + 3);     // LSU burst overlaps mma below
            ldfrag(Asl, Bsl, 1, af1, bf1);      // ks=1 LDS hides under ks=0 mma
            domma(af0, bf0, c);
            domma(af1, bf1, c);
        }
    }
};

// ===========================================================================
// GEMM1/2 (R13-verbatim apart from Core): chained slotted-A output.
// ===========================================================================
template <int MODE>
__global__ __launch_bounds__(128)
void gemm12_f16(const float* __restrict__ bias)
{
    extern __shared__ uint32_t sm[];
    const int tid  = threadIdx.x;
    const int lane = tid & 31;
    const int wid  = tid >> 5;
    const int tig  = lane & 3;
    const int wm   = wid >> 1;
    const int wn   = wid & 1;
    const int tile = blockIdx.x;
    const int col0 = blockIdx.y * 128;

    const uint32_t* srcA = (MODE == 0 ? g_A1 : g_A2) + (size_t)tile * 16 * BUFU;
    const uint32_t* srcB = (MODE == 0 ? g_WB1 : g_WB2) + (size_t)blockIdx.y * 16 * BUFU;
    uint32_t* dstA = (MODE == 0 ? g_A2 : g_A3) + (size_t)tile * 16 * BUFU;

    float c[4][8][4];
    #pragma unroll
    for (int i = 0; i < 4; i++)
        #pragma unroll
        for (int j = 0; j < 8; j++)
            #pragma unroll
            for (int q = 0; q < 4; q++) c[i][j][q] = 0.f;

    Core core{srcA, srcB,
              {sm, sm + BUFU, sm + 2 * BUFU, sm + 3 * BUFU},
              {sm + 4 * BUFU, sm + 5 * BUFU, sm + 6 * BUFU, sm + 7 * BUFU},
              tid, lane, wm, wn};
    core.run(c);

    #pragma unroll
    for (int mf = 0; mf < 4; mf++) {
        #pragma unroll
        for (int q = 0; q < 4; q++) {
            const int nf0 = 2 * q, nf1 = 2 * q + 1;
            const int K = col0 + wn * 64 + q * 16 + 2 * tig;
            const float b0 = bias[K],     b1 = bias[K + 1];
            const float b8 = bias[K + 8], b9 = bias[K + 9];
            const int kc_o = (col0 >> 5) + wn * 2 + (q >> 1);
            const int slot = (wm * 4 + mf) * 2 + (q & 1);
            uint4 v;
            v.x = pack_h2(lrelu(c[mf][nf0][0] + b0), lrelu(c[mf][nf0][1] + b1));
            v.y = pack_h2(lrelu(c[mf][nf0][2] + b0), lrelu(c[mf][nf0][3] + b1));
            v.z = pack_h2(lrelu(c[mf][nf1][0] + b8), lrelu(c[mf][nf1][1] + b9));
            v.w = pack_h2(lrelu(c[mf][nf1][2] + b8), lrelu(c[mf][nf1][3] + b9));
            *reinterpret_cast<uint4*>(
                &dstA[(size_t)(kc_o * 16 + slot) * SLOTU + lane * 4]) = v;
        }
    }
}

// ===========================================================================
// GEMM3 (R13-verbatim apart from Core).
// ===========================================================================
__global__ __launch_bounds__(128)
void gemm_head_tc(const float* __restrict__ bc1,
                  const float* __restrict__ Wc2,
                  float* __restrict__ logits)
{
    extern __shared__ uint32_t sm[];
    const int tid  = threadIdx.x;
    const int lane = tid & 31;
    const int wid  = tid >> 5;
    const int g    = lane >> 2;
    const int tig  = lane & 3;
    const int wm   = wid >> 1;
    const int wn   = wid & 1;
    const int tile = blockIdx.x;
    const int hb   = blockIdx.y;
    const int n    = blockIdx.z;
    const int row0 = tile * 128;
    const int h0   = hb * 128;

    const uint32_t* srcA = g_A3 + (size_t)tile * 16 * BUFU;
    const uint32_t* srcB = g_Bh + (size_t)(n * 4 + hb) * 16 * BUFU;

    float c[4][8][4];
    #pragma unroll
    for (int i = 0; i < 4; i++)
        #pragma unroll
        for (int j = 0; j < 8; j++)
            #pragma unroll
            for (int q = 0; q < 4; q++) c[i][j][q] = 0.f;

    Core core{srcA, srcB,
              {sm, sm + BUFU, sm + 2 * BUFU, sm + 3 * BUFU},
              {sm + 4 * BUFU, sm + 5 * BUFU, sm + 6 * BUFU, sm + 7 * BUFU},
              tid, lane, wm, wn};
    core.run(c);

    float p[8];
    #pragma unroll
    for (int i = 0; i < 8; i++) p[i] = 0.f;
    #pragma unroll
    for (int nf = 0; nf < 8; nf++) {
        int h = h0 + wn * 64 + nf * 8 + 2 * tig;
        float b1a = bc1[n * HH + h],     b1b = bc1[n * HH + h + 1];
        float w2a = Wc2[n * HH + h],     w2b = Wc2[n * HH + h + 1];
        #pragma unroll
        for (int mf = 0; mf < 4; mf++) {
            p[2 * mf + 0] += lrelu(c[mf][nf][0] + b1a) * w2a
                           + lrelu(c[mf][nf][1] + b1b) * w2b;
            p[2 * mf + 1] += lrelu(c[mf][nf][2] + b1a) * w2a
                           + lrelu(c[mf][nf][3] + b1b) * w2b;
        }
    }
    #pragma unroll
    for (int i = 0; i < 8; i++) {
        float v = p[i];
        v += __shfl_xor_sync(0xffffffffu, v, 1);
        v += __shfl_xor_sync(0xffffffffu, v, 2);
        if (tig == 0) {
            int mf = i >> 1, half = i & 1;
            int r = row0 + wm * 64 + mf * 16 + g + half * 8;
            int M = (r & 15) * 1024 + (r >> 4);
            atomicAdd(&logits[M * NN + n], v);
        }
    }
}

// full_out += bc2; out[b,n] = sigmoid(diagonal of full_out)
__global__ void finalize_kernel(float* __restrict__ out,
                                const float* __restrict__ bc2)
{
    int idx = blockIdx.x * 256 + threadIdx.x;      // < 262144
    int m = idx >> 4, n = idx & 15;
    float* full = out + MTOT;
    float v = full[idx] + bc2[n];
    full[idx] = v;
    if ((m >> 10) == n) {                           // m = n*1024 + b
        int b = m & 1023;
        out[b * NN + n] = 1.f / (1.f + expf(-v));
    }
}

extern "C" void kernel_launch(void* const* d_in, const int* in_sizes, int n_in,
                              void* d_out, int out_size)
{
    const float* x   = (const float*)d_in[0];
    const float* Ws1 = (const float*)d_in[1];
    const float* bs1 = (const float*)d_in[2];
    const float* Ws2 = (const float*)d_in[3];
    const float* bs2 = (const float*)d_in[4];
    const float* Wc1 = (const float*)d_in[5];
    const float* bc1 = (const float*)d_in[6];
    const float* Wc2 = (const float*)d_in[7];
    const float* bc2 = (const float*)d_in[8];
    float* out = (float*)d_out;

    cudaFuncSetAttribute(gemm12_f16<0>, cudaFuncAttributeMaxDynamicSharedMemorySize, RING_SMEM);
    cudaFuncSetAttribute(gemm12_f16<1>, cudaFuncAttributeMaxDynamicSharedMemorySize, RING_SMEM);
    cudaFuncSetAttribute(gemm_head_tc,  cudaFuncAttributeMaxDynamicSharedMemorySize, RING_SMEM);

    dim3 blk(256);
    prep_all_kernel<<<26624, blk>>>(x, Ws1, Ws2, Wc1, out);
    gemm12_f16<0><<<dim3(128, 4), dim3(128), RING_SMEM>>>(bs1);
    gemm12_f16<1><<<dim3(128, 4), dim3(128), RING_SMEM>>>(bs2);
    gemm_head_tc<<<dim3(128, 4, NN), dim3(128), RING_SMEM>>>(bc1, Wc2, out + MTOT);
    finalize_kernel<<<(MTOT * NN + 255) / 256, blk>>>(out, bc2);
}